// round 13
// baseline (speedup 1.0000x reference)
#include <cuda_runtime.h>
#include <cuda_fp16.h>

#define NMAX   100000
#define EMAX   1600000
#define DIN    64
#define NHEAD  4
#define HDIM   16
#define FEAT   64   // NHEAD*HDIM
#define SCAN_B 1024
#define NBMAX  256

// -------- scratch (static device globals; no allocations allowed) ----------
__device__ __align__(16) static __half g_h[(size_t)NMAX * FEAT];  // fp16 node features
__device__ __align__(16) static float2 g_uas[NMAX * NHEAD];  // (u, as_head) packed
__device__ __align__(16) static float2 g_vad[NMAX * NHEAD];  // (v+off, ad_head+ba) packed

// deg + publish-flags share one memset region: [0,NMAX) = deg, [NMAX,NMAX+NBMAX) = flags
__device__ static int g_degfv[NMAX + NBMAX];
__device__ static int g_cursor[NMAX];      // seeded with offs; scatter bumps it
__device__ static int g_offs[NMAX + 1];
__device__ static int g_srcs[EMAX];        // src node id per edge, sorted by dst

// ---------------------------------------------------------------------------
// 1) Degree histogram over dst, 4 edges/thread (deg zeroed by memsetAsync).
// ---------------------------------------------------------------------------
__global__ void hist_kernel(const int* __restrict__ dst, int E) {
    int q = blockIdx.x * blockDim.x + threadIdx.x;
    int e = q * 4;
    if (e + 3 < E) {
        int4 d4 = *reinterpret_cast<const int4*>(dst + e);
        atomicAdd(&g_degfv[d4.x], 1);
        atomicAdd(&g_degfv[d4.y], 1);
        atomicAdd(&g_degfv[d4.z], 1);
        atomicAdd(&g_degfv[d4.w], 1);
    } else {
        for (int k = e; k < E; k++) atomicAdd(&g_degfv[dst[k]], 1);
    }
}

// ---------------------------------------------------------------------------
// 2) Single-pass exclusive scan (98 co-resident blocks, aggregate lookback).
// ---------------------------------------------------------------------------
__global__ void scan_onepass_kernel(int N, int NB) {
    __shared__ int sm[SCAN_B];
    __shared__ int s_base;
    int b = blockIdx.x;
    int tid = threadIdx.x;
    int idx = b * SCAN_B + tid;

    int v = (idx < N) ? g_degfv[idx] : 0;
    sm[tid] = v;
    __syncthreads();
#pragma unroll
    for (int o = 1; o < SCAN_B; o <<= 1) {
        int tmp = (tid >= o) ? sm[tid - o] : 0;
        __syncthreads();
        sm[tid] += tmp;
        __syncthreads();
    }
    int incl = sm[tid];
    int agg = sm[SCAN_B - 1];

    if (tid == 0) {
        __threadfence();
        atomicExch(&g_degfv[NMAX + b], agg + 1);
    }

    if (tid < 32) {
        int contrib = 0;
        for (int t = tid; t < b; t += 32) {
            int fv;
            do { fv = atomicAdd(&g_degfv[NMAX + t], 0); } while (fv == 0);
            contrib += fv - 1;
        }
#pragma unroll
        for (int o = 16; o > 0; o >>= 1)
            contrib += __shfl_down_sync(0xffffffffu, contrib, o);
        if (tid == 0) s_base = contrib;
    }
    __syncthreads();
    int base = s_base;

    if (idx < N) {
        int off = base + incl - v;
        g_offs[idx] = off;
        g_cursor[idx] = off;
    }
    if (b == NB - 1 && tid == 0) g_offs[N] = base + agg;
}

// ---------------------------------------------------------------------------
// 3) Scatter src ids into dst-sorted order, 4 edges/thread.
// ---------------------------------------------------------------------------
__global__ void scatter_kernel(const int* __restrict__ src,
                               const int* __restrict__ dst, int E) {
    int q = blockIdx.x * blockDim.x + threadIdx.x;
    int e = q * 4;
    if (e + 3 < E) {
        int4 s4 = *reinterpret_cast<const int4*>(src + e);
        int4 d4 = *reinterpret_cast<const int4*>(dst + e);
        g_srcs[atomicAdd(&g_cursor[d4.x], 1)] = s4.x;
        g_srcs[atomicAdd(&g_cursor[d4.y], 1)] = s4.y;
        g_srcs[atomicAdd(&g_cursor[d4.z], 1)] = s4.z;
        g_srcs[atomicAdd(&g_cursor[d4.w], 1)] = s4.w;
    } else {
        for (int k = e; k < E; k++)
            g_srcs[atomicAdd(&g_cursor[dst[k]], 1)] = src[k];
    }
}

// ---------------------------------------------------------------------------
// 4) Per-node projections, with the rank-1 edge-linear fold computed
//    per block (fused former precompute_kernel). FFMA2 main matvec.
//    Outputs: g_h fp16, g_uas = (u, as_h), g_vad = (v+off, ad_h+ba).
// ---------------------------------------------------------------------------
__global__ void __launch_bounds__(128)
node_kernel(const float* __restrict__ x,
            const float* __restrict__ Wl,
            const float* __restrict__ bl,
            const float* __restrict__ Wa,
            const float* __restrict__ Wd,
            const float* __restrict__ bd,
            const float* __restrict__ Wf,
            const float* __restrict__ bf,
            const float* __restrict__ ba,
            int N) {
    __shared__ __align__(16) float s_wl[DIN * FEAT];
    __shared__ __align__(16) float s_bl[FEAT];
    __shared__ float s_wa[2 * HDIM];
    __shared__ float s_cu[DIN], s_cv[DIN];
    __shared__ float s_wfu[DIN], s_wfv[DIN];
    __shared__ float s_off, s_ba;

    int tid = threadIdx.x;
    for (int i = tid; i < DIN * FEAT; i += blockDim.x) s_wl[i] = Wl[i];
    if (tid < FEAT) s_bl[tid] = bl[tid];
    if (tid < 2 * HDIM) s_wa[tid] = Wa[tid];
    if (tid < DIN) {
        float f0 = Wf[tid], f1 = Wf[DIN + tid], f2 = Wf[2 * DIN + tid];
        s_wfu[tid] = f0 + f2;
        s_wfv[tid] = f1 - f2;
    }
    __syncthreads();
    // Fold: cu = Wd_row . wfu, cv = Wd_row . wfv  (64 rows on threads 0..63)
    if (tid < DIN) {
        float cu = 0.f, cv = 0.f;
        const float* wrow = Wd + tid * DIN;
#pragma unroll 8
        for (int j = 0; j < DIN; j++) {
            float w = __ldg(&wrow[j]);
            cu += w * s_wfu[j];
            cv += w * s_wfv[j];
        }
        s_cu[tid] = cu;
        s_cv[tid] = cv;
    }
    if (tid == 0) {
        float s = bf[0];
        for (int j = 0; j < DIN; j++) s += bd[j] * (s_wfu[j] + s_wfv[j]);
        s_off = s;
        s_ba  = ba[0];
    }
    __syncthreads();

    int n = blockIdx.x * blockDim.x + tid;
    if (n >= N) return;

    unsigned long long acc2[FEAT / 2];
    const ulonglong2* blp = reinterpret_cast<const ulonglong2*>(s_bl);
#pragma unroll
    for (int q = 0; q < FEAT / 4; q++) {
        ulonglong2 b2 = blp[q];
        acc2[q * 2 + 0] = b2.x;
        acc2[q * 2 + 1] = b2.y;
    }
    float u = 0.f, v = 0.f;

    const float4* xr = reinterpret_cast<const float4*>(x + (size_t)n * DIN);
#pragma unroll 1
    for (int i4 = 0; i4 < DIN / 4; i4++) {
        float4 xv = xr[i4];
        float xs[4] = {xv.x, xv.y, xv.z, xv.w};
#pragma unroll
        for (int j = 0; j < 4; j++) {
            int i = i4 * 4 + j;
            float xi = xs[j];
            u += xi * s_cu[i];
            v += xi * s_cv[i];
            unsigned long long xi2;
            asm("mov.b64 %0, {%1, %1};" : "=l"(xi2) : "f"(xi));
            const ulonglong2* wrow =
                reinterpret_cast<const ulonglong2*>(&s_wl[i * FEAT]);
#pragma unroll
            for (int q = 0; q < FEAT / 4; q++) {
                ulonglong2 wv = wrow[q];
                asm("fma.rn.f32x2 %0, %1, %2, %0;"
                    : "+l"(acc2[q * 2 + 0]) : "l"(wv.x), "l"(xi2));
                asm("fma.rn.f32x2 %0, %1, %2, %0;"
                    : "+l"(acc2[q * 2 + 1]) : "l"(wv.y), "l"(xi2));
            }
        }
    }

    float accf[FEAT];
#pragma unroll
    for (int k = 0; k < FEAT / 2; k++)
        asm("mov.b64 {%0, %1}, %2;"
            : "=f"(accf[2 * k]), "=f"(accf[2 * k + 1]) : "l"(acc2[k]));

    __half2* hout = reinterpret_cast<__half2*>(&g_h[(size_t)n * FEAT]);
#pragma unroll
    for (int o2 = 0; o2 < FEAT / 2; o2++)
        hout[o2] = __floats2half2_rn(accf[o2 * 2 + 0], accf[o2 * 2 + 1]);

    float voff = v + s_off;
#pragma unroll
    for (int h = 0; h < NHEAD; h++) {
        float as = 0.f, ad = 0.f;
#pragma unroll
        for (int k = 0; k < HDIM; k++) {
            float hv = accf[h * HDIM + k];
            as += hv * s_wa[k];
            ad += hv * s_wa[HDIM + k];
        }
        g_uas[n * NHEAD + h] = make_float2(u, as);
        g_vad[n * NHEAD + h] = make_float2(voff, ad + s_ba);
    }
}

// ---------------------------------------------------------------------------
// 5) CSR reduce: 4 threads per dst node. Lane t == head t, handling that
//    head's 16 fp16 features (two independent uint4 loads). A warp serves
//    8 nodes per iteration. No g_P dependency (constants folded into vad).
// ---------------------------------------------------------------------------
__global__ void __launch_bounds__(256)
reduce_kernel(float* __restrict__ out, int N) {
    int gid = blockIdx.x * blockDim.x + threadIdx.x;
    int n = gid >> 2;
    if (n >= N) return;
    int head = gid & 3;

    int beg = g_offs[n];
    int end = g_offs[n + 1];

    float2 vad = __ldg(&g_vad[n * NHEAD + head]);
    float vofs = vad.x;               // v + off
    float adb  = vad.y;               // ad + ba

    float acc[16];
#pragma unroll
    for (int k = 0; k < 16; k++) acc[k] = 0.f;
    float dsum = 0.f;

    if (beg < end) {
        int s = __ldg(&g_srcs[beg]);
        for (int p = beg; p < end; p++) {
            int s_next = (p + 1 < end) ? __ldg(&g_srcs[p + 1]) : 0;
            float2 ua = __ldg(&g_uas[s * NHEAD + head]);
            const uint4* hp = reinterpret_cast<const uint4*>(
                &g_h[(size_t)s * FEAT + head * HDIM]);
            uint4 raw0 = hp[0];
            uint4 raw1 = hp[1];

            float arg = ua.x + vofs;
            float sg = (arg > 0.f) ? 1.f : ((arg < 0.f) ? -1.f : 0.f);
            float al = sg * ua.y + adb;
            al = (al > 0.f) ? al : 0.01f * al;          // leaky_relu
            float w = __expf(al);
            float ws = w * sg;

            const __half2* c0 = reinterpret_cast<const __half2*>(&raw0);
            const __half2* c1 = reinterpret_cast<const __half2*>(&raw1);
#pragma unroll
            for (int q = 0; q < 4; q++) {
                float2 f0 = __half22float2(c0[q]);
                float2 f1 = __half22float2(c1[q]);
                acc[q * 2 + 0] += ws * f0.x;
                acc[q * 2 + 1] += ws * f0.y;
                acc[8 + q * 2 + 0] += ws * f1.x;
                acc[8 + q * 2 + 1] += ws * f1.y;
            }
            dsum += w;
            s = s_next;
        }
    }

    float inv = 1.f / fmaxf(dsum, 1e-16f);
    float* op = &out[(size_t)n * FEAT + head * HDIM];
#pragma unroll
    for (int q = 0; q < 4; q++)
        reinterpret_cast<float4*>(op)[q] =
            make_float4(acc[q * 4 + 0] * inv, acc[q * 4 + 1] * inv,
                        acc[q * 4 + 2] * inv, acc[q * 4 + 3] * inv);
}

// ---------------------------------------------------------------------------
extern "C" void kernel_launch(void* const* d_in, const int* in_sizes, int n_in,
                              void* d_out, int out_size) {
    const float* x   = (const float*)d_in[0];
    const int*   src = (const int*)  d_in[1];
    const int*   dst = (const int*)  d_in[2];
    const float* Wl  = (const float*)d_in[3];
    const float* bl  = (const float*)d_in[4];
    const float* Wa  = (const float*)d_in[5];
    const float* ba  = (const float*)d_in[6];
    const float* Wd  = (const float*)d_in[7];
    const float* bd  = (const float*)d_in[8];
    const float* Wf  = (const float*)d_in[9];
    const float* bf  = (const float*)d_in[10];
    float* out = (float*)d_out;

    int N = in_sizes[0] / DIN;
    int E = in_sizes[1];
    int NB = (N + SCAN_B - 1) / SCAN_B;

    // One-time stream/event setup (host resources, not device memory).
    static cudaStream_t s_side = nullptr;
    static cudaEvent_t  ev_fork = nullptr, ev_join = nullptr;
    static int* p_degfv = nullptr;
    if (s_side == nullptr) {
        cudaStreamCreateWithFlags(&s_side, cudaStreamNonBlocking);
        cudaEventCreateWithFlags(&ev_fork, cudaEventDisableTiming);
        cudaEventCreateWithFlags(&ev_join, cudaEventDisableTiming);
        cudaGetSymbolAddress((void**)&p_degfv, g_degfv);
    }

    // Fork: side stream builds the CSR while the main stream runs the
    // dense projections.
    cudaEventRecord(ev_fork, 0);
    cudaStreamWaitEvent(s_side, ev_fork, 0);

    cudaMemsetAsync(p_degfv, 0, (size_t)(N + NB) * sizeof(int), s_side);
    {
        int qthreads = (E + 3) / 4;
        hist_kernel<<<(qthreads + 255) / 256, 256, 0, s_side>>>(dst, E);
    }
    scan_onepass_kernel<<<NB, SCAN_B, 0, s_side>>>(N, NB);
    {
        int qthreads = (E + 3) / 4;
        scatter_kernel<<<(qthreads + 255) / 256, 256, 0, s_side>>>(src, dst, E);
    }
    cudaEventRecord(ev_join, s_side);

    node_kernel<<<(N + 127) / 128, 128>>>(x, Wl, bl, Wa, Wd, bd, Wf, bf, ba, N);

    // Join, then reduce (4 threads per node).
    cudaStreamWaitEvent(0, ev_join, 0);
    long long threads = (long long)N * 4;
    int blocks = (int)((threads + 255) / 256);
    reduce_kernel<<<blocks, 256>>>(out, N);
}

// round 14
// speedup vs baseline: 1.1940x; 1.1940x over previous
#include <cuda_runtime.h>
#include <cuda_fp16.h>

#define NMAX   100000
#define EMAX   1600000
#define DIN    64
#define NHEAD  4
#define HDIM   16
#define FEAT   64   // NHEAD*HDIM
#define SCAN_B 1024
#define NBMAX  256

// -------- scratch (static device globals; no allocations allowed) ----------
__device__ __align__(16) static __half g_h[(size_t)NMAX * FEAT];  // fp16 node features
__device__ __align__(16) static float2 g_uas[NMAX * NHEAD];  // (u, as_head) packed
__device__ __align__(16) static float2 g_vad[NMAX * NHEAD];  // (v+off, ad_head+ba) packed

// deg + publish-flags share one memset region: [0,NMAX) = deg, [NMAX,NMAX+NBMAX) = flags
__device__ static int g_degfv[NMAX + NBMAX];
__device__ static int g_cursor[NMAX];      // seeded with offs; scatter bumps it
__device__ static int g_offs[NMAX + 1];
__device__ static int g_srcs[EMAX];        // src node id per edge, sorted by dst

struct Params {
    float cu[DIN];
    float cv[DIN];
    float off;
    float ba;
};
__device__ static Params g_P;

// ---------------------------------------------------------------------------
// 1) Fold the rank-1 edge linears (512 threads, 8-way K-split + shfl).
// ---------------------------------------------------------------------------
__global__ void __launch_bounds__(512)
precompute_kernel(const float* __restrict__ Wd,
                  const float* __restrict__ bd,
                  const float* __restrict__ Wf,
                  const float* __restrict__ bf,
                  const float* __restrict__ ba) {
    __shared__ float wfu[DIN], wfv[DIN], red[DIN];
    int tid = threadIdx.x;
    if (tid < DIN) {
        float f0 = Wf[tid], f1 = Wf[DIN + tid], f2 = Wf[2 * DIN + tid];
        wfu[tid] = f0 + f2;
        wfv[tid] = f1 - f2;
        red[tid] = bd[tid] * (wfu[tid] + wfv[tid]);
    }
    __syncthreads();

    int r = tid >> 3;
    int part = tid & 7;
    float cu = 0.f, cv = 0.f;
#pragma unroll
    for (int jj = 0; jj < 8; jj++) {
        int j = part * 8 + jj;
        float w = Wd[r * DIN + j];
        cu += w * wfu[j];
        cv += w * wfv[j];
    }
#pragma unroll
    for (int o = 4; o > 0; o >>= 1) {
        cu += __shfl_down_sync(0xffffffffu, cu, o);
        cv += __shfl_down_sync(0xffffffffu, cv, o);
    }
    if (part == 0) {
        g_P.cu[r] = cu;
        g_P.cv[r] = cv;
    }
    if (tid == 0) {
        float s = bf[0];
        for (int j = 0; j < DIN; j++) s += red[j];
        g_P.off = s;
        g_P.ba  = ba[0];
    }
}

// ---------------------------------------------------------------------------
// 2) Degree histogram over dst, 4 edges/thread (deg zeroed by memsetAsync).
// ---------------------------------------------------------------------------
__global__ void hist_kernel(const int* __restrict__ dst, int E) {
    int q = blockIdx.x * blockDim.x + threadIdx.x;
    int e = q * 4;
    if (e + 3 < E) {
        int4 d4 = *reinterpret_cast<const int4*>(dst + e);
        atomicAdd(&g_degfv[d4.x], 1);
        atomicAdd(&g_degfv[d4.y], 1);
        atomicAdd(&g_degfv[d4.z], 1);
        atomicAdd(&g_degfv[d4.w], 1);
    } else {
        for (int k = e; k < E; k++) atomicAdd(&g_degfv[dst[k]], 1);
    }
}

// ---------------------------------------------------------------------------
// 3) Single-pass exclusive scan (98 co-resident blocks, aggregate lookback).
// ---------------------------------------------------------------------------
__global__ void scan_onepass_kernel(int N, int NB) {
    __shared__ int sm[SCAN_B];
    __shared__ int s_base;
    int b = blockIdx.x;
    int tid = threadIdx.x;
    int idx = b * SCAN_B + tid;

    int v = (idx < N) ? g_degfv[idx] : 0;
    sm[tid] = v;
    __syncthreads();
#pragma unroll
    for (int o = 1; o < SCAN_B; o <<= 1) {
        int tmp = (tid >= o) ? sm[tid - o] : 0;
        __syncthreads();
        sm[tid] += tmp;
        __syncthreads();
    }
    int incl = sm[tid];
    int agg = sm[SCAN_B - 1];

    if (tid == 0) {
        __threadfence();
        atomicExch(&g_degfv[NMAX + b], agg + 1);
    }

    if (tid < 32) {
        int contrib = 0;
        for (int t = tid; t < b; t += 32) {
            int fv;
            do { fv = atomicAdd(&g_degfv[NMAX + t], 0); } while (fv == 0);
            contrib += fv - 1;
        }
#pragma unroll
        for (int o = 16; o > 0; o >>= 1)
            contrib += __shfl_down_sync(0xffffffffu, contrib, o);
        if (tid == 0) s_base = contrib;
    }
    __syncthreads();
    int base = s_base;

    if (idx < N) {
        int off = base + incl - v;
        g_offs[idx] = off;
        g_cursor[idx] = off;
    }
    if (b == NB - 1 && tid == 0) g_offs[N] = base + agg;
}

// ---------------------------------------------------------------------------
// 4) Scatter src ids into dst-sorted order, 4 edges/thread.
// ---------------------------------------------------------------------------
__global__ void scatter_kernel(const int* __restrict__ src,
                               const int* __restrict__ dst, int E) {
    int q = blockIdx.x * blockDim.x + threadIdx.x;
    int e = q * 4;
    if (e + 3 < E) {
        int4 s4 = *reinterpret_cast<const int4*>(src + e);
        int4 d4 = *reinterpret_cast<const int4*>(dst + e);
        g_srcs[atomicAdd(&g_cursor[d4.x], 1)] = s4.x;
        g_srcs[atomicAdd(&g_cursor[d4.y], 1)] = s4.y;
        g_srcs[atomicAdd(&g_cursor[d4.z], 1)] = s4.z;
        g_srcs[atomicAdd(&g_cursor[d4.w], 1)] = s4.w;
    } else {
        for (int k = e; k < E; k++)
            g_srcs[atomicAdd(&g_cursor[dst[k]], 1)] = src[k];
    }
}

// ---------------------------------------------------------------------------
// 5) Per-node projections, TWO nodes per thread: each smem weight load feeds
//    FFMA2s for both nodes -> LDS bytes per node halved (the measured
//    bottleneck). Outputs: g_h fp16, g_uas=(u,as_h), g_vad=(v+off, ad_h+ba).
// ---------------------------------------------------------------------------
__global__ void __launch_bounds__(128)
node_kernel(const float* __restrict__ x,
            const float* __restrict__ Wl,
            const float* __restrict__ bl,
            const float* __restrict__ Wa,
            int N) {
    __shared__ __align__(16) float s_wl[DIN * FEAT];
    __shared__ __align__(16) float s_bl[FEAT];
    __shared__ float s_wa[2 * HDIM];
    __shared__ float s_cu[DIN], s_cv[DIN];

    int tid = threadIdx.x;
    for (int i = tid; i < DIN * FEAT; i += blockDim.x) s_wl[i] = Wl[i];
    if (tid < FEAT) {
        s_bl[tid] = bl[tid];
        s_cu[tid] = g_P.cu[tid];
        s_cv[tid] = g_P.cv[tid];
    }
    if (tid < 2 * HDIM) s_wa[tid] = Wa[tid];
    __syncthreads();

    int n0 = blockIdx.x * 256 + tid;
    int n1 = n0 + 128;
    if (n0 >= N) return;
    bool ok1 = (n1 < N);
    int n1r = ok1 ? n1 : n0;       // safe read index for the x row

    unsigned long long accA[FEAT / 2], accB[FEAT / 2];
    const ulonglong2* blp = reinterpret_cast<const ulonglong2*>(s_bl);
#pragma unroll
    for (int q = 0; q < FEAT / 4; q++) {
        ulonglong2 b2 = blp[q];
        accA[q * 2 + 0] = b2.x;  accA[q * 2 + 1] = b2.y;
        accB[q * 2 + 0] = b2.x;  accB[q * 2 + 1] = b2.y;
    }
    float uA = 0.f, vA = 0.f, uB = 0.f, vB = 0.f;

    const float4* xrA = reinterpret_cast<const float4*>(x + (size_t)n0 * DIN);
    const float4* xrB = reinterpret_cast<const float4*>(x + (size_t)n1r * DIN);
#pragma unroll 1
    for (int i4 = 0; i4 < DIN / 4; i4++) {
        float4 xa = xrA[i4];
        float4 xb = xrB[i4];
        float xsA[4] = {xa.x, xa.y, xa.z, xa.w};
        float xsB[4] = {xb.x, xb.y, xb.z, xb.w};
#pragma unroll
        for (int j = 0; j < 4; j++) {
            int i = i4 * 4 + j;
            float xiA = xsA[j], xiB = xsB[j];
            uA += xiA * s_cu[i];  vA += xiA * s_cv[i];
            uB += xiB * s_cu[i];  vB += xiB * s_cv[i];
            unsigned long long xa2, xb2;
            asm("mov.b64 %0, {%1, %1};" : "=l"(xa2) : "f"(xiA));
            asm("mov.b64 %0, {%1, %1};" : "=l"(xb2) : "f"(xiB));
            const ulonglong2* wrow =
                reinterpret_cast<const ulonglong2*>(&s_wl[i * FEAT]);
#pragma unroll
            for (int q = 0; q < FEAT / 4; q++) {
                ulonglong2 wv = wrow[q];
                asm("fma.rn.f32x2 %0, %1, %2, %0;"
                    : "+l"(accA[q * 2 + 0]) : "l"(wv.x), "l"(xa2));
                asm("fma.rn.f32x2 %0, %1, %2, %0;"
                    : "+l"(accA[q * 2 + 1]) : "l"(wv.y), "l"(xa2));
                asm("fma.rn.f32x2 %0, %1, %2, %0;"
                    : "+l"(accB[q * 2 + 0]) : "l"(wv.x), "l"(xb2));
                asm("fma.rn.f32x2 %0, %1, %2, %0;"
                    : "+l"(accB[q * 2 + 1]) : "l"(wv.y), "l"(xb2));
            }
        }
    }

    float off = g_P.off, bav = g_P.ba;

    // ---- node n0 ----
    {
        float accf[FEAT];
#pragma unroll
        for (int k = 0; k < FEAT / 2; k++)
            asm("mov.b64 {%0, %1}, %2;"
                : "=f"(accf[2 * k]), "=f"(accf[2 * k + 1]) : "l"(accA[k]));
        __half2* hout = reinterpret_cast<__half2*>(&g_h[(size_t)n0 * FEAT]);
#pragma unroll
        for (int o2 = 0; o2 < FEAT / 2; o2++)
            hout[o2] = __floats2half2_rn(accf[o2 * 2 + 0], accf[o2 * 2 + 1]);
        float voff = vA + off;
#pragma unroll
        for (int h = 0; h < NHEAD; h++) {
            float as = 0.f, ad = 0.f;
#pragma unroll
            for (int k = 0; k < HDIM; k++) {
                float hv = accf[h * HDIM + k];
                as += hv * s_wa[k];
                ad += hv * s_wa[HDIM + k];
            }
            g_uas[n0 * NHEAD + h] = make_float2(uA, as);
            g_vad[n0 * NHEAD + h] = make_float2(voff, ad + bav);
        }
    }
    // ---- node n1 ----
    if (ok1) {
        float accf[FEAT];
#pragma unroll
        for (int k = 0; k < FEAT / 2; k++)
            asm("mov.b64 {%0, %1}, %2;"
                : "=f"(accf[2 * k]), "=f"(accf[2 * k + 1]) : "l"(accB[k]));
        __half2* hout = reinterpret_cast<__half2*>(&g_h[(size_t)n1 * FEAT]);
#pragma unroll
        for (int o2 = 0; o2 < FEAT / 2; o2++)
            hout[o2] = __floats2half2_rn(accf[o2 * 2 + 0], accf[o2 * 2 + 1]);
        float voff = vB + off;
#pragma unroll
        for (int h = 0; h < NHEAD; h++) {
            float as = 0.f, ad = 0.f;
#pragma unroll
            for (int k = 0; k < HDIM; k++) {
                float hv = accf[h * HDIM + k];
                as += hv * s_wa[k];
                ad += hv * s_wa[HDIM + k];
            }
            g_uas[n1 * NHEAD + h] = make_float2(uB, as);
            g_vad[n1 * NHEAD + h] = make_float2(voff, ad + bav);
        }
    }
}

// ---------------------------------------------------------------------------
// 6) CSR reduce: 4 threads per dst node. Lane t == head t (16 fp16 features,
//    two independent uint4 loads). No global-constant loads (folded into vad).
// ---------------------------------------------------------------------------
__global__ void __launch_bounds__(256)
reduce_kernel(float* __restrict__ out, int N) {
    int gid = blockIdx.x * blockDim.x + threadIdx.x;
    int n = gid >> 2;
    if (n >= N) return;
    int head = gid & 3;

    int beg = g_offs[n];
    int end = g_offs[n + 1];

    float2 vad = __ldg(&g_vad[n * NHEAD + head]);
    float vofs = vad.x;
    float adb  = vad.y;

    float acc[16];
#pragma unroll
    for (int k = 0; k < 16; k++) acc[k] = 0.f;
    float dsum = 0.f;

    if (beg < end) {
        int s = __ldg(&g_srcs[beg]);
        for (int p = beg; p < end; p++) {
            int s_next = (p + 1 < end) ? __ldg(&g_srcs[p + 1]) : 0;
            float2 ua = __ldg(&g_uas[s * NHEAD + head]);
            const uint4* hp = reinterpret_cast<const uint4*>(
                &g_h[(size_t)s * FEAT + head * HDIM]);
            uint4 raw0 = hp[0];
            uint4 raw1 = hp[1];

            float arg = ua.x + vofs;
            float sg = (arg > 0.f) ? 1.f : ((arg < 0.f) ? -1.f : 0.f);
            float al = sg * ua.y + adb;
            al = (al > 0.f) ? al : 0.01f * al;          // leaky_relu
            float w = __expf(al);
            float ws = w * sg;

            const __half2* c0 = reinterpret_cast<const __half2*>(&raw0);
            const __half2* c1 = reinterpret_cast<const __half2*>(&raw1);
#pragma unroll
            for (int q = 0; q < 4; q++) {
                float2 f0 = __half22float2(c0[q]);
                float2 f1 = __half22float2(c1[q]);
                acc[q * 2 + 0] += ws * f0.x;
                acc[q * 2 + 1] += ws * f0.y;
                acc[8 + q * 2 + 0] += ws * f1.x;
                acc[8 + q * 2 + 1] += ws * f1.y;
            }
            dsum += w;
            s = s_next;
        }
    }

    float inv = 1.f / fmaxf(dsum, 1e-16f);
    float* op = &out[(size_t)n * FEAT + head * HDIM];
#pragma unroll
    for (int q = 0; q < 4; q++)
        reinterpret_cast<float4*>(op)[q] =
            make_float4(acc[q * 4 + 0] * inv, acc[q * 4 + 1] * inv,
                        acc[q * 4 + 2] * inv, acc[q * 4 + 3] * inv);
}

// ---------------------------------------------------------------------------
extern "C" void kernel_launch(void* const* d_in, const int* in_sizes, int n_in,
                              void* d_out, int out_size) {
    const float* x   = (const float*)d_in[0];
    const int*   src = (const int*)  d_in[1];
    const int*   dst = (const int*)  d_in[2];
    const float* Wl  = (const float*)d_in[3];
    const float* bl  = (const float*)d_in[4];
    const float* Wa  = (const float*)d_in[5];
    const float* ba  = (const float*)d_in[6];
    const float* Wd  = (const float*)d_in[7];
    const float* bd  = (const float*)d_in[8];
    const float* Wf  = (const float*)d_in[9];
    const float* bf  = (const float*)d_in[10];
    float* out = (float*)d_out;

    int N = in_sizes[0] / DIN;
    int E = in_sizes[1];
    int NB = (N + SCAN_B - 1) / SCAN_B;

    // One-time stream/event setup (host resources, not device memory).
    static cudaStream_t s_side = nullptr;
    static cudaEvent_t  ev_fork = nullptr, ev_join = nullptr;
    static int* p_degfv = nullptr;
    if (s_side == nullptr) {
        cudaStreamCreateWithFlags(&s_side, cudaStreamNonBlocking);
        cudaEventCreateWithFlags(&ev_fork, cudaEventDisableTiming);
        cudaEventCreateWithFlags(&ev_join, cudaEventDisableTiming);
        cudaGetSymbolAddress((void**)&p_degfv, g_degfv);
    }

    cudaEventRecord(ev_fork, 0);
    cudaStreamWaitEvent(s_side, ev_fork, 0);

    cudaMemsetAsync(p_degfv, 0, (size_t)(N + NB) * sizeof(int), s_side);
    {
        int qthreads = (E + 3) / 4;
        hist_kernel<<<(qthreads + 255) / 256, 256, 0, s_side>>>(dst, E);
    }
    scan_onepass_kernel<<<NB, SCAN_B, 0, s_side>>>(N, NB);
    {
        int qthreads = (E + 3) / 4;
        scatter_kernel<<<(qthreads + 255) / 256, 256, 0, s_side>>>(src, dst, E);
    }
    cudaEventRecord(ev_join, s_side);

    precompute_kernel<<<1, 512>>>(Wd, bd, Wf, bf, ba);
    node_kernel<<<(N + 255) / 256, 128>>>(x, Wl, bl, Wa, N);

    cudaStreamWaitEvent(0, ev_join, 0);
    long long threads = (long long)N * 4;
    int blocks = (int)((threads + 255) / 256);
    reduce_kernel<<<blocks, 256>>>(out, N);
}